// round 13
// baseline (speedup 1.0000x reference)
#include <cuda_runtime.h>
#include <math_constants.h>

// ============================================================
// ChamferLoss via exact 2-D (x,y)-binned sorted-window NN.
//  - bucket-sort both clouds by (xbin, ybin), 64x64 bins
//    (points of one x-row are contiguous; y-rect = one range per row)
//  - query kernel, ONE WARP PER QUERY:
//      seed: smallest r with non-empty (2r+1)^2 rect -> scan -> d0
//      exact: rect [xbin(qx+-d0)] x [ybin(qy+-d0)] (+-1 pad); outside
//             rect => |dx|>d0 or |dy|>d0 => cannot beat best. Exact.
//    Warp-uniform loops; lane-strided coalesced float4 loads.
//  - scan_kernel zeroes g_bincnt after use -> no init kernel, 6 launches.
//  - single writer per query into g_dist[orig] -> bit-deterministic.
// ============================================================

#define XB 64
#define YB 64
#define NBINS (XB * YB)              // 4096
#define GRID_LO (-6.0f)
#define BINW 0.1875f                 // 12/64
#define INV_BINW (64.0f / 12.0f)
#define MAXPTS 16384
#define RED_CTAS 64
#define RED_THREADS 256

__device__ float4 g_sorted[2][MAXPTS];
__device__ int    g_bincnt[2][NBINS];       // zero-init BSS; re-zeroed by scan
__device__ int    g_binstart[2][NBINS + 1];
__device__ int    g_curs[2][NBINS];
__device__ float  g_dist[2 * MAXPTS];
__device__ float  g_part[RED_CTAS];

__device__ __forceinline__ int bcoord(float v) {
    int b = (int)((v - GRID_LO) * INV_BINW);
    return min(max(b, 0), XB - 1);
}

// ---------- 1. histogram by (xbin, ybin) ----------
__global__ void hist_kernel(const float* __restrict__ A,
                            const float* __restrict__ B, int N, int M) {
    int gid = blockIdx.x * blockDim.x + threadIdx.x;
    if (gid >= N + M) return;
    int cl = (gid >= N);
    int i = cl ? gid - N : gid;
    const float* src = cl ? B : A;
    int key = bcoord(src[3 * i]) * YB + bcoord(src[3 * i + 1]);
    atomicAdd(&g_bincnt[cl][key], 1);
}

// ---------- 2. per-cloud exclusive scan over 4096 bins (one CTA) ----------
// Also zeroes g_bincnt for the next graph replay.
__global__ void __launch_bounds__(1024)
scan_kernel() {
    __shared__ int s[1024];
    const int tid = threadIdx.x;
    const int CPT = (2 * NBINS) / 1024;     // 8 flattened bins per thread
    const int base = tid * CPT;

    int c[CPT], sum = 0;
    #pragma unroll
    for (int i = 0; i < CPT; i++) {
        c[i] = ((int*)g_bincnt)[base + i];
        ((int*)g_bincnt)[base + i] = 0;      // reset for next replay
        sum += c[i];
    }
    s[tid] = sum;
    __syncthreads();
    #pragma unroll
    for (int off = 1; off < 1024; off <<= 1) {
        int v = (tid >= off) ? s[tid - off] : 0;
        __syncthreads();
        s[tid] += v;
        __syncthreads();
    }
    // threads [0,512) hold cloud 0, [512,1024) cloud 1 (4096 bins each)
    const int cloud_off = (tid >= 512) ? s[511] : 0;
    int run = (s[tid] - sum) - cloud_off;
    #pragma unroll
    for (int i = 0; i < CPT; i++) {
        int g = base + i;
        int cl = g >> 12, b = g & (NBINS - 1);
        g_binstart[cl][b] = run;
        g_curs[cl][b] = run;
        run += c[i];
    }
    if (tid == 511)  g_binstart[0][NBINS] = s[511];
    if (tid == 1023) g_binstart[1][NBINS] = s[1023] - s[511];
}

// ---------- 3. scatter into (x,y)-sorted order (orig index in .w) ----------
__global__ void scatter_kernel(const float* __restrict__ A,
                               const float* __restrict__ B, int N, int M) {
    int gid = blockIdx.x * blockDim.x + threadIdx.x;
    if (gid >= N + M) return;
    int cl = (gid >= N);
    int i = cl ? gid - N : gid;
    const float* src = cl ? B : A;
    float x = src[3 * i], y = src[3 * i + 1], z = src[3 * i + 2];
    int key = bcoord(x) * YB + bcoord(y);
    int pos = atomicAdd(&g_curs[cl][key], 1);
    g_sorted[cl][pos] = make_float4(x, y, z, __int_as_float(i));
}

// ---------- 4. exact two-phase NN, one warp per query ----------
__global__ void __launch_bounds__(256)
query_kernel(int N, int M) {
    const int gw = (blockIdx.x * blockDim.x + threadIdx.x) >> 5;
    const int lane = threadIdx.x & 31;
    if (gw >= N + M) return;
    const int cl = (gw >= N);
    const int i = cl ? gw - N : gw;
    const int ct = 1 - cl;

    const float4 p = g_sorted[cl][i];       // broadcast load
    const float qx = p.x, qy = p.y, qz = p.z;
    const int* __restrict__ bs = g_binstart[ct];
    const float4* __restrict__ pts = g_sorted[ct];
    const int xb = bcoord(qx), yb = bcoord(qy);

    // seed: smallest r with non-empty (2r+1)^2 rect (count via prefix diffs)
    int r = 1;
    int xlo, xhi, ylo, yhi;
    for (;;) {
        xlo = max(xb - r, 0); xhi = min(xb + r, XB - 1);
        ylo = max(yb - r, 0); yhi = min(yb + r, YB - 1);
        int cnt = 0;
        for (int xr = xlo; xr <= xhi; xr++)
            cnt += bs[xr * YB + yhi + 1] - bs[xr * YB + ylo];
        if (cnt > 0) break;
        r++;
    }
    float best = CUDART_INF_F;
    for (int xr = xlo; xr <= xhi; xr++) {
        const int s = bs[xr * YB + ylo];
        const int e = bs[xr * YB + yhi + 1];
        for (int k = s + lane; k < e; k += 32) {
            float4 t = pts[k];
            float dx = qx - t.x, dy = qy - t.y, dz = qz - t.z;
            best = fminf(best, fmaf(dx, dx, fmaf(dy, dy, dz * dz)));
        }
    }
    #pragma unroll
    for (int o = 16; o > 0; o >>= 1)
        best = fminf(best, __shfl_xor_sync(0xFFFFFFFFu, best, o));

    // exact rect: |dx|<=d0 AND |dy|<=d0 points all lie inside (+-1 pad);
    // anything outside has |dx|>d0 or |dy|>d0 => dist > d0 >= final best.
    const float d0 = sqrtf(best);
    const int xlo2 = max(bcoord(qx - d0) - 1, 0);
    const int xhi2 = min(bcoord(qx + d0) + 1, XB - 1);
    const int ylo2 = max(bcoord(qy - d0) - 1, 0);
    const int yhi2 = min(bcoord(qy + d0) + 1, YB - 1);
    if (xlo2 < xlo || xhi2 > xhi || ylo2 < ylo || yhi2 > yhi) {
        for (int xr = xlo2; xr <= xhi2; xr++) {
            const int s = bs[xr * YB + ylo2];
            const int e = bs[xr * YB + yhi2 + 1];
            for (int k = s + lane; k < e; k += 32) {
                float4 t = pts[k];
                float dx = qx - t.x, dy = qy - t.y, dz = qz - t.z;
                best = fminf(best, fmaf(dx, dx, fmaf(dy, dy, dz * dz)));
            }
        }
        #pragma unroll
        for (int o = 16; o > 0; o >>= 1)
            best = fminf(best, __shfl_xor_sync(0xFFFFFFFFu, best, o));
    }

    if (lane == 0)
        g_dist[(cl ? N : 0) + __float_as_int(p.w)] = sqrtf(best);
}

// ---------- 5-6. deterministic two-stage sum ----------
__global__ void __launch_bounds__(RED_THREADS)
reduce1_kernel(int total) {
    __shared__ float ssum[RED_THREADS / 32];
    const int per = (total + RED_CTAS - 1) / RED_CTAS;
    const int base = blockIdx.x * per;
    const int end = min(base + per, total);

    float acc = 0.0f;
    for (int i = base + threadIdx.x; i < end; i += RED_THREADS)
        acc += g_dist[i];
    #pragma unroll
    for (int o = 16; o > 0; o >>= 1)
        acc += __shfl_down_sync(0xFFFFFFFFu, acc, o);
    if ((threadIdx.x & 31) == 0) ssum[threadIdx.x >> 5] = acc;
    __syncthreads();
    if (threadIdx.x == 0) {
        float v = 0.0f;
        #pragma unroll
        for (int w = 0; w < RED_THREADS / 32; w++) v += ssum[w];
        g_part[blockIdx.x] = v;
    }
}

__global__ void reduce2_kernel(float* __restrict__ out) {
    float acc = 0.0f;
    #pragma unroll
    for (int k = 0; k < RED_CTAS / 32; k++)
        acc += g_part[threadIdx.x + 32 * k];
    #pragma unroll
    for (int o = 16; o > 0; o >>= 1)
        acc += __shfl_down_sync(0xFFFFFFFFu, acc, o);
    if (threadIdx.x == 0) out[0] = acc * 0.001f;
}

extern "C" void kernel_launch(void* const* d_in, const int* in_sizes, int n_in,
                              void* d_out, int out_size)
{
    const float* A = (const float*)d_in[0];   // target_pc [N,3]
    const float* B = (const float*)d_in[1];   // output_pc [M,3]
    const int N = in_sizes[0] / 3;
    const int M = in_sizes[1] / 3;
    const int total = N + M;

    hist_kernel<<<(total + 255) / 256, 256>>>(A, B, N, M);
    scan_kernel<<<1, 1024>>>();
    scatter_kernel<<<(total + 255) / 256, 256>>>(A, B, N, M);
    query_kernel<<<(total * 32 + 255) / 256, 256>>>(N, M);   // warp / query
    reduce1_kernel<<<RED_CTAS, RED_THREADS>>>(total);
    reduce2_kernel<<<1, 32>>>((float*)d_out);
}